// round 13
// baseline (speedup 1.0000x reference)
#include <cuda_runtime.h>
#include <cstdint>

// 3D spatial correlation sampler, patch=7, dil=1, k=1, s=1, pad=0
// in1,in2: [B=2, C=32, D=32, H=32, W=32] fp32
// out: [B, 7, 7, 7, D, H, W] fp32
//
// Grid = (b, d, hq, od) -> 1792 blocks. 256 threads, WARP-SPECIALIZED:
// warps 0-6 = consumers (warp = oh), warp 7 = producer (all cp.async
// staging: in1 tile once + in2 slab per 8-channel chunk, double-buffered).
// mbarrier pipeline (full: cp.async.mbarrier.arrive.noinc, count 32;
// empty: consumer arrive, count 224) — NO __syncthreads in the mainloop.
// Inner math: pair-aligned fma.rn.f32x2, conflict-free pitches 36/44.

#define BB 2
#define CC 32
#define DD 32
#define HH 32
#define WW 32
#define PP 7
#define TH 8
#define NTHREADS 256
#define NCONS 224                 // consumer threads (7 warps)
#define CCHUNK 8
#define NCHUNK (CC / CCHUNK)      // 4

#define IN1_PITCH 36                               // step mod 32 = 4 -> conflict-free
#define IN1_SZ (CC * TH * IN1_PITCH)               // 9216 floats
#define SLAB_ROWS (TH + 6)                         // 14
#define SLAB_PITCH 44                              // step mod 32 = 12 -> conflict-free
#define SLABC_SZ (CCHUNK * SLAB_ROWS * SLAB_PITCH) // 4928 floats per buf
// smem floats: [0,16) barriers (4 x u64 + pad), [16,...) in1, then 2 slab bufs
#define BAR_FLOATS 16
#define IN1_OFF BAR_FLOATS
#define SLAB_OFF (IN1_OFF + IN1_SZ)
#define SMEM_FLOATS (SLAB_OFF + 2 * SLABC_SZ)      // 19088 floats = 76352 B

typedef unsigned long long u64;

__device__ __forceinline__ void cp_async16(uint32_t dst, const void* src, int src_bytes) {
    asm volatile("cp.async.cg.shared.global [%0], [%1], 16, %2;\n"
                 :: "r"(dst), "l"(src), "r"(src_bytes));
}
__device__ __forceinline__ void mbar_init(uint32_t addr, uint32_t count) {
    asm volatile("mbarrier.init.shared.b64 [%0], %1;" :: "r"(addr), "r"(count) : "memory");
}
__device__ __forceinline__ void mbar_arrive(uint32_t addr) {
    asm volatile("mbarrier.arrive.shared.b64 _, [%0];" :: "r"(addr) : "memory");
}
__device__ __forceinline__ void cp_async_arrive(uint32_t addr) {
    asm volatile("cp.async.mbarrier.arrive.noinc.shared.b64 [%0];" :: "r"(addr) : "memory");
}
__device__ __forceinline__ void mbar_wait(uint32_t addr, int phase) {
    asm volatile(
        "{\n\t.reg .pred P;\n\t"
        "WL_%=:\n\t"
        "mbarrier.try_wait.parity.acquire.cta.shared::cta.b64 P, [%0], %1, 0x989680;\n\t"
        "@P bra.uni WD_%=;\n\t"
        "bra.uni WL_%=;\n\t"
        "WD_%=:\n\t}"
        :: "r"(addr), "r"(phase) : "memory");
}
__device__ __forceinline__ void ffma2(u64& acc, u64 a, u64 b) {
    asm("fma.rn.f32x2 %0, %1, %2, %0;" : "+l"(acc) : "l"(a), "l"(b));
}
// O = (hi32(lo_src), lo32(hi_src))
__device__ __forceinline__ u64 mix_hi_lo(u64 lo_src, u64 hi_src) {
    uint32_t a0, a1, b0, b1;
    asm("mov.b64 {%0,%1}, %2;" : "=r"(a0), "=r"(a1) : "l"(lo_src));
    asm("mov.b64 {%0,%1}, %2;" : "=r"(b0), "=r"(b1) : "l"(hi_src));
    u64 r;
    asm("mov.b64 %0, {%1,%2};" : "=l"(r) : "r"(a1), "r"(b0));
    return r;
}

__global__ __launch_bounds__(NTHREADS, 2)
void corr3d_kernel(const float* __restrict__ in1,
                   const float* __restrict__ in2,
                   float* __restrict__ out)
{
    extern __shared__ float sm[];

    int bx = blockIdx.x;            // ((b*32 + d)*4 + hq)*7 + od
    const int od = bx % 7;   bx /= 7;
    const int hq = bx & 3;   bx >>= 2;
    const int d  = bx & 31;
    const int b  = bx >> 5;
    const int h0 = hq * TH;

    const int t    = threadIdx.x;
    const int lane = t & 31;
    const int wid  = t >> 5;        // 0..6 consumers (oh = wid), 7 producer
    const int hl   = lane & 7;
    const int wi   = lane >> 3;
    const int w0   = wi * 8;

    const int z = d + od - 3;       // uniform per block
    const bool zvalid = (z >= 0) && (z < DD);

    const uint32_t smem_u32 = (uint32_t)__cvta_generic_to_shared(sm);
    // barriers: full0 @0, full1 @8, empty0 @16, empty1 @24 (bytes)
    const uint32_t FULL0 = smem_u32, FULL1 = smem_u32 + 8;
    const uint32_t EMPT0 = smem_u32 + 16, EMPT1 = smem_u32 + 24;

    if (zvalid) {
        if (t == 0) {
            mbar_init(FULL0, 32);  mbar_init(FULL1, 32);
            mbar_init(EMPT0, NCONS); mbar_init(EMPT1, NCONS);
        }
        __syncthreads();   // barriers visible before any arrive/wait

        if (wid == 7) {
            // ================= PRODUCER =================
            const float* in1g = in1 + ((size_t)(b * CC) * DD + d) * (HH * WW);
            const float* in2g = in2 + ((size_t)(b * CC) * DD + z) * (HH * WW);
            const uint32_t in1b = smem_u32 + IN1_OFF * 4u;
            const uint32_t slab0 = smem_u32 + SLAB_OFF * 4u;

            // in1 tile: 2048 float4 slots over 32 lanes
            #pragma unroll 4
            for (int i = 0; i < 64; i++) {
                int slot = i * 32 + lane;
                int c    = slot >> 6;
                int rem  = slot & 63;
                int hh   = rem >> 3;
                int w4   = (rem & 7) * 4;
                cp_async16(in1b + (uint32_t)(c * (TH * IN1_PITCH)
                                             + hh * IN1_PITCH + w4) * 4u,
                           in1g + (size_t)c * (DD * HH * WW) + (h0 + hh) * WW + w4,
                           16);
            }

            for (int ch = 0; ch < NCHUNK; ch++) {
                if (ch >= 2) mbar_wait((ch & 1) ? EMPT1 : EMPT0, 0);

                const float* g2 = in2g + (size_t)(ch * CCHUNK) * (DD * HH * WW);
                uint32_t slabb = slab0 + (uint32_t)((ch & 1) * SLABC_SZ) * 4u;
                #pragma unroll 5
                for (int i = 0; i < 35; i++) {       // 1120 slots / 32 lanes
                    int slot = i * 32 + lane;
                    int c    = slot / 140;
                    int rem  = slot - c * 140;
                    int r    = rem / 10;
                    int s4   = rem - r * 10;
                    int hg   = h0 + r - 3;
                    bool v   = (s4 >= 1) && (s4 <= 8) && (hg >= 0) && (hg < HH);
                    const float* src = v ? (g2 + (size_t)c * (DD * HH * WW)
                                               + hg * WW + (s4 - 1) * 4)
                                         : g2;       // clamped dummy, zfilled
                    cp_async16(slabb + (uint32_t)(c * (SLAB_ROWS * SLAB_PITCH)
                                                  + r * SLAB_PITCH + s4 * 4) * 4u,
                               src, v ? 16 : 0);
                }
                // arrival fires when ALL this thread's prior cp.asyncs land
                cp_async_arrive((ch & 1) ? FULL1 : FULL0);
            }
            return;   // producer done
        }

        // ================= CONSUMERS (warps 0-6, oh = wid) =================
        const int oh = wid;

        u64 acc2[PP][4];
        #pragma unroll
        for (int pw = 0; pw < PP; pw++)
            #pragma unroll
            for (int j = 0; j < 4; j++) acc2[pw][j] = 0ull;

        for (int ch = 0; ch < NCHUNK; ch++) {
            mbar_wait((ch & 1) ? FULL1 : FULL0, ch >> 1);

            const float* ap = sm + IN1_OFF + ch * (CCHUNK * TH * IN1_PITCH)
                                 + hl * IN1_PITCH + w0;
            const float* bp = sm + SLAB_OFF + (ch & 1) * SLABC_SZ
                                 + (hl + oh) * SLAB_PITCH + w0;

            #pragma unroll
            for (int c = 0; c < CCHUNK; c++) {
                ulonglong2 a01 = *(const ulonglong2*)(ap);      // av[0..3]
                ulonglong2 a23 = *(const ulonglong2*)(ap + 4);  // av[4..7]
                ulonglong2 e0  = *(const ulonglong2*)(bp);      // bb[0..3]
                ulonglong2 e1  = *(const ulonglong2*)(bp + 4);  // bb[4..7]
                ulonglong2 e2  = *(const ulonglong2*)(bp + 8);  // bb[8..11]
                ulonglong2 e3  = *(const ulonglong2*)(bp + 12); // bb[12..15]

                u64 A[4] = {a01.x, a01.y, a23.x, a23.y};
                u64 E[8] = {e0.x, e0.y, e1.x, e1.y, e2.x, e2.y, e3.x, e3.y};
                u64 O[7];                       // O[m] = (bb[2m+1], bb[2m+2])
                #pragma unroll
                for (int m = 0; m < 7; m++) O[m] = mix_hi_lo(E[m], E[m + 1]);

                // B pair start k = pw+1+2j; even k -> E[k/2], odd -> O[k/2]
                #pragma unroll
                for (int pw = 0; pw < PP; pw++)
                    #pragma unroll
                    for (int j = 0; j < 4; j++) {
                        const int k = pw + 1 + 2 * j;
                        ffma2(acc2[pw][j], A[j], (k & 1) ? O[k >> 1] : E[k >> 1]);
                    }

                ap += TH * IN1_PITCH;
                bp += SLAB_ROWS * SLAB_PITCH;
            }

            if (ch < 2) mbar_arrive((ch & 1) ? EMPT1 : EMPT0);  // release buf
        }

        // ---- store ----
        size_t obase = (size_t)(((b * PP + od) * PP + oh) * PP) * (DD * HH * WW)
                     + (size_t)d * (HH * WW) + (h0 + hl) * WW + w0;
        #pragma unroll
        for (int pw = 0; pw < PP; pw++) {
            float* o = out + obase + (size_t)pw * (DD * HH * WW);
            *(ulonglong2*)(o)     = make_ulonglong2(acc2[pw][0], acc2[pw][1]);
            *(ulonglong2*)(o + 4) = make_ulonglong2(acc2[pw][2], acc2[pw][3]);
        }
        return;
    }

    // ---- z out of range: consumers store zeros, producer idles ----
    if (wid < 7) {
        const int oh = wid;
        size_t obase = (size_t)(((b * PP + od) * PP + oh) * PP) * (DD * HH * WW)
                     + (size_t)d * (HH * WW) + (h0 + hl) * WW + w0;
        const ulonglong2 z2 = make_ulonglong2(0ull, 0ull);
        #pragma unroll
        for (int pw = 0; pw < PP; pw++) {
            float* o = out + obase + (size_t)pw * (DD * HH * WW);
            *(ulonglong2*)(o)     = z2;
            *(ulonglong2*)(o + 4) = z2;
        }
    }
}

extern "C" void kernel_launch(void* const* d_in, const int* in_sizes, int n_in,
                              void* d_out, int out_size)
{
    const float* in1 = (const float*)d_in[0];
    const float* in2 = (const float*)d_in[1];
    float* out = (float*)d_out;

    cudaFuncSetAttribute(corr3d_kernel,
                         cudaFuncAttributeMaxDynamicSharedMemorySize,
                         SMEM_FLOATS * sizeof(float));

    dim3 grid(BB * DD * 4 * PP);   // 1792
    dim3 block(NTHREADS);
    corr3d_kernel<<<grid, block, SMEM_FLOATS * sizeof(float)>>>(in1, in2, out);
}

// round 14
// speedup vs baseline: 1.2870x; 1.2870x over previous
#include <cuda_runtime.h>
#include <cstdint>

// 3D spatial correlation sampler, patch=7, dil=1, k=1, s=1, pad=0
// in1,in2: [B=2, C=32, D=32, H=32, W=32] fp32
// out: [B, 7, 7, 7, D, H, W] fp32
//
// FINAL (R7 config — best measured). Grid = (b, d, hq, od) -> 1792 blocks;
// 224 threads = 7 warps, warp = oh. Channels in 4 chunks of 8, double-
// buffered cp.async (zfill halo). Inner math: packed fma.rn.f32x2 with
// PAIR-ALIGNED operands — smem loaded as ulonglong2 so A-pairs and even
// B-pairs are free; only the 7 odd B-pairs cost 2 MOVs each.
// Conflict-free smem pitches (36 / 44). 2 CTAs/SM, 128-reg budget.

#define BB 2
#define CC 32
#define DD 32
#define HH 32
#define WW 32
#define PP 7
#define TH 8
#define NTHREADS 224
#define CCHUNK 8
#define NCHUNK (CC / CCHUNK)     // 4

#define IN1_PITCH 36                               // step mod 32 = 4 -> conflict-free
#define IN1C_SZ (CCHUNK * TH * IN1_PITCH)          // 2304 floats
#define SLAB_ROWS (TH + 6)                         // 14
#define SLAB_PITCH 44                              // step mod 32 = 12 -> conflict-free
#define SLABC_SZ (CCHUNK * SLAB_ROWS * SLAB_PITCH) // 4928 floats
#define BUF_SZ (IN1C_SZ + SLABC_SZ)                // 7232 floats
#define SMEM_FLOATS (2 * BUF_SZ)                   // 57856 B

typedef unsigned long long u64;

__device__ __forceinline__ void cp_async16(uint32_t dst, const void* src, int src_bytes) {
    asm volatile("cp.async.cg.shared.global [%0], [%1], 16, %2;\n"
                 :: "r"(dst), "l"(src), "r"(src_bytes));
}
__device__ __forceinline__ void ffma2(u64& acc, u64 a, u64 b) {
    asm("fma.rn.f32x2 %0, %1, %2, %0;" : "+l"(acc) : "l"(a), "l"(b));
}
// O = (hi32(lo_src), lo32(hi_src)) — unpacks are register aliases
__device__ __forceinline__ u64 mix_hi_lo(u64 lo_src, u64 hi_src) {
    uint32_t a0, a1, b0, b1;
    asm("mov.b64 {%0,%1}, %2;" : "=r"(a0), "=r"(a1) : "l"(lo_src));
    asm("mov.b64 {%0,%1}, %2;" : "=r"(b0), "=r"(b1) : "l"(hi_src));
    u64 r;
    asm("mov.b64 %0, {%1,%2};" : "=l"(r) : "r"(a1), "r"(b0));
    return r;
}

__global__ __launch_bounds__(NTHREADS, 2)
void corr3d_kernel(const float* __restrict__ in1,
                   const float* __restrict__ in2,
                   float* __restrict__ out)
{
    extern __shared__ float sm[];   // 2 buffers: [in1 2304 | slab 4928] each

    int bx = blockIdx.x;            // ((b*32 + d)*4 + hq)*7 + od
    const int od = bx % 7;   bx /= 7;
    const int hq = bx & 3;   bx >>= 2;
    const int d  = bx & 31;
    const int b  = bx >> 5;
    const int h0 = hq * TH;

    const int t    = threadIdx.x;
    const int lane = t & 31;
    const int oh   = t >> 5;        // warp id = oh
    const int hl   = lane & 7;
    const int wi   = lane >> 3;
    const int w0   = wi * 8;

    const int z = d + od - 3;       // uniform per block
    const bool zvalid = (z >= 0) && (z < DD);

    // acc2[pw][j] packs outputs (w0+2j, w0+2j+1)
    u64 acc2[PP][4];
    #pragma unroll
    for (int pw = 0; pw < PP; pw++)
        #pragma unroll
        for (int j = 0; j < 4; j++) acc2[pw][j] = 0ull;

    if (zvalid) {
        const float* in1g = in1 + ((size_t)(b * CC) * DD + d) * (HH * WW);
        const float* in2g = in2 + ((size_t)(b * CC) * DD + z) * (HH * WW);
        const uint32_t smem_u32 = (uint32_t)__cvta_generic_to_shared(sm);

        auto stage = [&](int chunk, int buf) {
            const float* g1 = in1g + (size_t)(chunk * CCHUNK) * (DD * HH * WW);
            const float* g2 = in2g + (size_t)(chunk * CCHUNK) * (DD * HH * WW);
            uint32_t in1b  = smem_u32 + (uint32_t)(buf * BUF_SZ) * 4u;
            uint32_t slabb = in1b + IN1C_SZ * 4u;

            #pragma unroll
            for (int i = 0; i < 3; i++) {
                int slot = i * NTHREADS + t;
                if (slot < CCHUNK * TH * 8) {
                    int c   = slot >> 6;
                    int rem = slot & 63;
                    int hh  = rem >> 3;
                    int w4  = (rem & 7) * 4;
                    cp_async16(in1b + (uint32_t)(c * (TH * IN1_PITCH)
                                                 + hh * IN1_PITCH + w4) * 4u,
                               g1 + (size_t)c * (DD * HH * WW) + (h0 + hh) * WW + w4,
                               16);
                }
            }
            #pragma unroll
            for (int i = 0; i < 5; i++) {
                int slot = i * NTHREADS + t;
                int c    = slot / 140;
                int rem  = slot - c * 140;
                int r    = rem / 10;
                int s4   = rem - r * 10;
                int hg   = h0 + r - 3;
                bool v   = (s4 >= 1) && (s4 <= 8) && (hg >= 0) && (hg < HH);
                const float* src = v ? (g2 + (size_t)c * (DD * HH * WW)
                                           + hg * WW + (s4 - 1) * 4)
                                     : g2;       // clamped dummy, zfilled
                cp_async16(slabb + (uint32_t)(c * (SLAB_ROWS * SLAB_PITCH)
                                              + r * SLAB_PITCH + s4 * 4) * 4u,
                           src, v ? 16 : 0);
            }
            asm volatile("cp.async.commit_group;\n" ::);
        };

        stage(0, 0);
        asm volatile("cp.async.wait_group 0;\n" ::);
        __syncthreads();

        for (int ch = 0; ch < NCHUNK; ch++) {
            if (ch + 1 < NCHUNK) stage(ch + 1, (ch + 1) & 1);

            const float* bufp = sm + (ch & 1) * BUF_SZ;
            const float* ap = bufp + hl * IN1_PITCH + w0;
            const float* bp = bufp + IN1C_SZ + (hl + oh) * SLAB_PITCH + w0;

            #pragma unroll
            for (int c = 0; c < CCHUNK; c++) {
                ulonglong2 a01 = *(const ulonglong2*)(ap);      // av[0..3]
                ulonglong2 a23 = *(const ulonglong2*)(ap + 4);  // av[4..7]
                ulonglong2 e0  = *(const ulonglong2*)(bp);      // bb[0..3]
                ulonglong2 e1  = *(const ulonglong2*)(bp + 4);  // bb[4..7]
                ulonglong2 e2  = *(const ulonglong2*)(bp + 8);  // bb[8..11]
                ulonglong2 e3  = *(const ulonglong2*)(bp + 12); // bb[12..15]

                u64 A[4] = {a01.x, a01.y, a23.x, a23.y};
                u64 E[8] = {e0.x, e0.y, e1.x, e1.y, e2.x, e2.y, e3.x, e3.y};
                u64 O[7];                       // O[m] = (bb[2m+1], bb[2m+2])
                #pragma unroll
                for (int m = 0; m < 7; m++) O[m] = mix_hi_lo(E[m], E[m + 1]);

                // B pair start k = pw+1+2j; even k -> E[k/2], odd -> O[k/2]
                #pragma unroll
                for (int pw = 0; pw < PP; pw++)
                    #pragma unroll
                    for (int j = 0; j < 4; j++) {
                        const int k = pw + 1 + 2 * j;
                        ffma2(acc2[pw][j], A[j], (k & 1) ? O[k >> 1] : E[k >> 1]);
                    }

                ap += TH * IN1_PITCH;
                bp += SLAB_ROWS * SLAB_PITCH;
            }

            if (ch + 1 < NCHUNK) {
                asm volatile("cp.async.wait_group 0;\n" ::);
                __syncthreads();
            }
        }
    }

    // ---- store (zeros if z OOB); u64 pairs are bit-identical to float2 ----
    size_t obase = (size_t)(((b * PP + od) * PP + oh) * PP) * (DD * HH * WW)
                 + (size_t)d * (HH * WW) + (h0 + hl) * WW + w0;
    #pragma unroll
    for (int pw = 0; pw < PP; pw++) {
        float* o = out + obase + (size_t)pw * (DD * HH * WW);
        *(ulonglong2*)(o)     = make_ulonglong2(acc2[pw][0], acc2[pw][1]);
        *(ulonglong2*)(o + 4) = make_ulonglong2(acc2[pw][2], acc2[pw][3]);
    }
}

extern "C" void kernel_launch(void* const* d_in, const int* in_sizes, int n_in,
                              void* d_out, int out_size)
{
    const float* in1 = (const float*)d_in[0];
    const float* in2 = (const float*)d_in[1];
    float* out = (float*)d_out;

    cudaFuncSetAttribute(corr3d_kernel,
                         cudaFuncAttributeMaxDynamicSharedMemorySize,
                         SMEM_FLOATS * sizeof(float));

    dim3 grid(BB * DD * 4 * PP);   // 1792
    dim3 block(NTHREADS);
    corr3d_kernel<<<grid, block, SMEM_FLOATS * sizeof(float)>>>(in1, in2, out);
}

// round 15
// speedup vs baseline: 1.3332x; 1.0359x over previous
#include <cuda_runtime.h>
#include <cstdint>

// 3D spatial correlation sampler, patch=7, dil=1, k=1, s=1, pad=0
// in1,in2: [B=2, C=32, D=32, H=32, W=32] fp32
// out: [B, 7, 7, 7, D, H, W] fp32
//
// Grid = (b, d, hq, od) -> 1792 blocks; 224 threads = 7 warps, warp = oh.
// ZERO-BARRIER mainloop: all 4 slab chunks cp.async'd in the prologue into
// 4 distinct buffers (no reuse); per-chunk mbarriers (count 224, async
// arrive) replace every mid-loop __syncthreads, so warps decouple fully.
// in1 is read directly via LDG (lane remap hl=lane>>2/wi=lane&3 makes the
// global reads full-density 128B rows) — no in1 staging at all.
// Inner math: pair-aligned fma.rn.f32x2; slab pitch 44 conflict-free.

#define BB 2
#define CC 32
#define DD 32
#define HH 32
#define WW 32
#define PP 7
#define TH 8
#define NTHREADS 224
#define CCHUNK 8
#define NCHUNK (CC / CCHUNK)      // 4

#define SLAB_ROWS (TH + 6)                         // 14
#define SLAB_PITCH 44                              // conflict-free under new map
#define SLABC_SZ (CCHUNK * SLAB_ROWS * SLAB_PITCH) // 4928 floats per buf
#define BAR_FLOATS 16                              // 4 mbarriers + pad
#define SLAB_OFF BAR_FLOATS
#define SMEM_FLOATS (SLAB_OFF + NCHUNK * SLABC_SZ) // 19728 floats = 78912 B

typedef unsigned long long u64;

__device__ __forceinline__ void cp_async16(uint32_t dst, const void* src, int src_bytes) {
    asm volatile("cp.async.cg.shared.global [%0], [%1], 16, %2;\n"
                 :: "r"(dst), "l"(src), "r"(src_bytes));
}
__device__ __forceinline__ void mbar_init(uint32_t addr, uint32_t count) {
    asm volatile("mbarrier.init.shared.b64 [%0], %1;" :: "r"(addr), "r"(count) : "memory");
}
__device__ __forceinline__ void cp_async_arrive(uint32_t addr) {
    asm volatile("cp.async.mbarrier.arrive.noinc.shared.b64 [%0];" :: "r"(addr) : "memory");
}
__device__ __forceinline__ void mbar_wait(uint32_t addr, int phase) {
    asm volatile(
        "{\n\t.reg .pred P;\n\t"
        "WL_%=:\n\t"
        "mbarrier.try_wait.parity.acquire.cta.shared::cta.b64 P, [%0], %1, 0x989680;\n\t"
        "@P bra.uni WD_%=;\n\t"
        "bra.uni WL_%=;\n\t"
        "WD_%=:\n\t}"
        :: "r"(addr), "r"(phase) : "memory");
}
__device__ __forceinline__ void ffma2(u64& acc, u64 a, u64 b) {
    asm("fma.rn.f32x2 %0, %1, %2, %0;" : "+l"(acc) : "l"(a), "l"(b));
}
// O = (hi32(lo_src), lo32(hi_src))
__device__ __forceinline__ u64 mix_hi_lo(u64 lo_src, u64 hi_src) {
    uint32_t a0, a1, b0, b1;
    asm("mov.b64 {%0,%1}, %2;" : "=r"(a0), "=r"(a1) : "l"(lo_src));
    asm("mov.b64 {%0,%1}, %2;" : "=r"(b0), "=r"(b1) : "l"(hi_src));
    u64 r;
    asm("mov.b64 %0, {%1,%2};" : "=l"(r) : "r"(a1), "r"(b0));
    return r;
}

__global__ __launch_bounds__(NTHREADS, 2)
void corr3d_kernel(const float* __restrict__ in1,
                   const float* __restrict__ in2,
                   float* __restrict__ out)
{
    extern __shared__ float sm[];   // [4 mbars | slab buf0..buf3]

    int bx = blockIdx.x;            // ((b*32 + d)*4 + hq)*7 + od
    const int od = bx % 7;   bx /= 7;
    const int hq = bx & 3;   bx >>= 2;
    const int d  = bx & 31;
    const int b  = bx >> 5;
    const int h0 = hq * TH;

    const int t    = threadIdx.x;
    const int lane = t & 31;
    const int oh   = t >> 5;        // warp id = oh
    const int hl   = lane >> 2;     // 0..7  (REMAPPED: 4 lanes per h-row)
    const int wi   = lane & 3;      // 0..3
    const int w0   = wi * 8;

    const int z = d + od - 3;       // uniform per block
    const bool zvalid = (z >= 0) && (z < DD);

    // acc2[pw][j] packs outputs (w0+2j, w0+2j+1)
    u64 acc2[PP][4];
    #pragma unroll
    for (int pw = 0; pw < PP; pw++)
        #pragma unroll
        for (int j = 0; j < 4; j++) acc2[pw][j] = 0ull;

    if (zvalid) {
        const float* in1g = in1 + ((size_t)(b * CC) * DD + d) * (HH * WW)
                                + (h0 + hl) * WW + w0;
        const float* in2g = in2 + ((size_t)(b * CC) * DD + z) * (HH * WW);
        const uint32_t smem_u32 = (uint32_t)__cvta_generic_to_shared(sm);
        const uint32_t slab0 = smem_u32 + SLAB_OFF * 4u;

        if (t == 0) {
            #pragma unroll
            for (int ch = 0; ch < NCHUNK; ch++)
                mbar_init(smem_u32 + 8u * ch, NTHREADS);
        }
        __syncthreads();   // mbarriers visible before any arrive

        // ---- prologue: stage ALL 4 slab chunks, arrive per chunk ----
        #pragma unroll
        for (int ch = 0; ch < NCHUNK; ch++) {
            const float* g2 = in2g + (size_t)(ch * CCHUNK) * (DD * HH * WW);
            uint32_t slabb = slab0 + (uint32_t)(ch * SLABC_SZ) * 4u;
            #pragma unroll
            for (int i = 0; i < 5; i++) {
                int slot = i * NTHREADS + t;            // 0..1119
                int c    = slot / 140;
                int rem  = slot - c * 140;
                int r    = rem / 10;
                int s4   = rem - r * 10;
                int hg   = h0 + r - 3;
                bool v   = (s4 >= 1) && (s4 <= 8) && (hg >= 0) && (hg < HH);
                const float* src = v ? (g2 + (size_t)c * (DD * HH * WW)
                                           + hg * WW + (s4 - 1) * 4)
                                     : g2;       // clamped dummy, zfilled
                cp_async16(slabb + (uint32_t)(c * (SLAB_ROWS * SLAB_PITCH)
                                              + r * SLAB_PITCH + s4 * 4) * 4u,
                           src, v ? 16 : 0);
            }
            cp_async_arrive(smem_u32 + 8u * ch);   // fires when copies land
        }

        // ---- mainloop: NO __syncthreads; warps proceed independently ----
        for (int ch = 0; ch < NCHUNK; ch++) {
            mbar_wait(smem_u32 + 8u * ch, 0);

            const float* ap = in1g + (size_t)(ch * CCHUNK) * (DD * HH * WW);
            const float* bp = sm + SLAB_OFF + ch * SLABC_SZ
                                 + (hl + oh) * SLAB_PITCH + w0;

            #pragma unroll
            for (int c = 0; c < CCHUNK; c++) {
                // in1 direct from global (L2-hit; full-density 128B rows)
                ulonglong2 a01 = *(const ulonglong2*)(ap);      // av[0..3]
                ulonglong2 a23 = *(const ulonglong2*)(ap + 4);  // av[4..7]
                ulonglong2 e0  = *(const ulonglong2*)(bp);      // bb[0..3]
                ulonglong2 e1  = *(const ulonglong2*)(bp + 4);  // bb[4..7]
                ulonglong2 e2  = *(const ulonglong2*)(bp + 8);  // bb[8..11]
                ulonglong2 e3  = *(const ulonglong2*)(bp + 12); // bb[12..15]

                u64 A[4] = {a01.x, a01.y, a23.x, a23.y};
                u64 E[8] = {e0.x, e0.y, e1.x, e1.y, e2.x, e2.y, e3.x, e3.y};
                u64 O[7];                       // O[m] = (bb[2m+1], bb[2m+2])
                #pragma unroll
                for (int m = 0; m < 7; m++) O[m] = mix_hi_lo(E[m], E[m + 1]);

                // B pair start k = pw+1+2j; even k -> E[k/2], odd -> O[k/2]
                #pragma unroll
                for (int pw = 0; pw < PP; pw++)
                    #pragma unroll
                    for (int j = 0; j < 4; j++) {
                        const int k = pw + 1 + 2 * j;
                        ffma2(acc2[pw][j], A[j], (k & 1) ? O[k >> 1] : E[k >> 1]);
                    }

                ap += DD * HH * WW;
                bp += SLAB_ROWS * SLAB_PITCH;
            }
        }
    }

    // ---- store (zeros if z OOB); u64 pairs are bit-identical to float2 ----
    size_t obase = (size_t)(((b * PP + od) * PP + oh) * PP) * (DD * HH * WW)
                 + (size_t)d * (HH * WW) + (h0 + hl) * WW + w0;
    #pragma unroll
    for (int pw = 0; pw < PP; pw++) {
        float* o = out + obase + (size_t)pw * (DD * HH * WW);
        *(ulonglong2*)(o)     = make_ulonglong2(acc2[pw][0], acc2[pw][1]);
        *(ulonglong2*)(o + 4) = make_ulonglong2(acc2[pw][2], acc2[pw][3]);
    }
}

extern "C" void kernel_launch(void* const* d_in, const int* in_sizes, int n_in,
                              void* d_out, int out_size)
{
    const float* in1 = (const float*)d_in[0];
    const float* in2 = (const float*)d_in[1];
    float* out = (float*)d_out;

    cudaFuncSetAttribute(corr3d_kernel,
                         cudaFuncAttributeMaxDynamicSharedMemorySize,
                         SMEM_FLOATS * sizeof(float));

    dim3 grid(BB * DD * 4 * PP);   // 1792
    dim3 block(NTHREADS);
    corr3d_kernel<<<grid, block, SMEM_FLOATS * sizeof(float)>>>(in1, in2, out);
}